// round 17
// baseline (speedup 1.0000x reference)
#include <cuda_runtime.h>
#include <cuda_bf16.h>
#include <stdint.h>
#include <math.h>

// ---------------------------------------------------------------------------
// Problem constants
// ---------------------------------------------------------------------------
#define BB   2
#define SS   1025
#define DD   1024
#define HH_  16
#define HD_  64
#define PP   1024
#define KR_  32
#define SCALE_ 0.125f
#define INV_TEMP 10.0f

// ---------------------------------------------------------------------------
// Scratch
// ---------------------------------------------------------------------------
static const size_t F_QR   = 2048ull * 1024;
static const size_t F_KR   = 2048ull * 1024;
static const size_t F_SC   = 2048ull * 1024;
static const size_t F_SC2  = 2048ull * 1024;
static const size_t F_QKV  = 2050ull * 3072;
static const size_t F_LW   = 2048ull * 32;
static const size_t F_RT   = 2048ull * 32;
static const size_t F_P1   = 2050ull * 1024;
static const size_t F_P2   = 2050ull * 1024;
static const size_t H_XN   = 2050ull * 1024 / 2;
static const size_t H_QKR  = 4096ull * 1024 / 2;
static const size_t H_ATT  = 2050ull * 1024 / 2;
static const size_t H_HN   = 2050ull * 1024 / 2;
static const size_t H_HH   = 2050ull * 4096 / 2;
static const size_t H_W    = 14680064ull / 2;

static const size_t O_QR   = 0;
static const size_t O_KR   = O_QR  + F_QR;
static const size_t O_SC   = O_KR  + F_KR;
static const size_t O_SC2  = O_SC  + F_SC;
static const size_t O_QKV  = O_SC2 + F_SC2;
static const size_t O_LW   = O_QKV + F_QKV;
static const size_t O_RT   = O_LW  + F_LW;
static const size_t O_P1   = O_RT  + F_RT;
static const size_t O_P2   = O_P1  + F_P1;
static const size_t O_XNH  = O_P2  + F_P2;
static const size_t O_XNL  = O_XNH + H_XN;
static const size_t O_QKRH = O_XNL + H_XN;
static const size_t O_QKRL = O_QKRH + H_QKR;
static const size_t O_ATTH = O_QKRL + H_QKR;
static const size_t O_ATTL = O_ATTH + H_ATT;
static const size_t O_HNH  = O_ATTL + H_ATT;
static const size_t O_HNL  = O_HNH + H_HN;
static const size_t O_HHH  = O_HNL + H_HN;
static const size_t O_HHL  = O_HHH + H_HH;
static const size_t O_WH   = O_HHL + H_HH;
static const size_t O_WL   = O_WH  + H_W;
static const size_t SCR_TOTAL = O_WL + H_W;

static const size_t W_RQ   = 0;
static const size_t W_RK   = 1048576;
static const size_t W_QKV  = 2097152;
static const size_t W_PROJ = 5242880;
static const size_t W_FC1  = 6291456;
static const size_t W_FC2  = 10485760;

__device__ float g_scratch[SCR_TOTAL];

// ---------------------------------------------------------------------------
// Block reductions
// ---------------------------------------------------------------------------
__device__ __forceinline__ float blockReduceSum(float v, float* sbuf) {
    int lane = threadIdx.x & 31, wid = threadIdx.x >> 5;
    #pragma unroll
    for (int o = 16; o; o >>= 1) v += __shfl_xor_sync(0xffffffffu, v, o);
    if (lane == 0) sbuf[wid] = v;
    __syncthreads();
    if (wid == 0) {
        v = (lane < 8) ? sbuf[lane] : 0.f;
        #pragma unroll
        for (int o = 4; o; o >>= 1) v += __shfl_xor_sync(0xffffffffu, v, o);
        if (lane == 0) sbuf[0] = v;
    }
    __syncthreads();
    float r = sbuf[0];
    __syncthreads();
    return r;
}

__device__ __forceinline__ float blockReduceSum512(float v, float* sbuf) {
    int lane = threadIdx.x & 31, wid = threadIdx.x >> 5;
    #pragma unroll
    for (int o = 16; o; o >>= 1) v += __shfl_xor_sync(0xffffffffu, v, o);
    if (lane == 0) sbuf[wid] = v;
    __syncthreads();
    if (wid == 0) {
        v = (lane < 16) ? sbuf[lane] : 0.f;
        #pragma unroll
        for (int o = 8; o; o >>= 1) v += __shfl_xor_sync(0xffffffffu, v, o);
        if (lane == 0) sbuf[0] = v;
    }
    __syncthreads();
    float r = sbuf[0];
    __syncthreads();
    return r;
}

__device__ __forceinline__ float blockReduceMax512(float v, float* sbuf) {
    int lane = threadIdx.x & 31, wid = threadIdx.x >> 5;
    #pragma unroll
    for (int o = 16; o; o >>= 1) v = fmaxf(v, __shfl_xor_sync(0xffffffffu, v, o));
    if (lane == 0) sbuf[wid] = v;
    __syncthreads();
    if (wid == 0) {
        v = (lane < 16) ? sbuf[lane] : -3.4e38f;
        #pragma unroll
        for (int o = 8; o; o >>= 1) v = fmaxf(v, __shfl_xor_sync(0xffffffffu, v, o));
        if (lane == 0) sbuf[0] = v;
    }
    __syncthreads();
    float r = sbuf[0];
    __syncthreads();
    return r;
}

__device__ __forceinline__ void split1(float v, __nv_bfloat16* hi, __nv_bfloat16* lo) {
    __nv_bfloat16 h = __float2bfloat16(v);
    *hi = h;
    *lo = __float2bfloat16(v - __bfloat162float(h));
}

// ---------------------------------------------------------------------------
// Merged: LayerNorm1 (blocks 0..2049) + weight split (blocks 2050..4097)
// ---------------------------------------------------------------------------
struct WSplit6 {
    const float* src[6];
    long dstoff[6];
    int n4[6];
};

__global__ void ln1_splitw_kernel(WSplit6 a,
                                  __nv_bfloat16* __restrict__ whi,
                                  __nv_bfloat16* __restrict__ wlo,
                                  const float* __restrict__ in,
                                  const float* __restrict__ w,
                                  const float* __restrict__ b,
                                  __nv_bfloat16* __restrict__ outh,
                                  __nv_bfloat16* __restrict__ outl) {
    __shared__ float red[32];
    const int tid = threadIdx.x;
    if (blockIdx.x < 2050) {
        const int row = blockIdx.x;
        const float4* ip = (const float4*)(in + (size_t)row * 1024);
        float4 v = ip[tid];
        float s = v.x + v.y + v.z + v.w;
        float mean = blockReduceSum(s, red) * (1.f / 1024.f);
        float dx = v.x - mean, dy = v.y - mean, dz = v.z - mean, dw = v.w - mean;
        float ss = dx * dx + dy * dy + dz * dz + dw * dw;
        float var = blockReduceSum(ss, red) * (1.f / 1024.f);
        float rstd = rsqrtf(var + 1e-5f);
        float4 wv = ((const float4*)w)[tid];
        float4 bv = ((const float4*)b)[tid];
        float ox = dx * rstd * wv.x + bv.x;
        float oy = dy * rstd * wv.y + bv.y;
        float oz = dz * rstd * wv.z + bv.z;
        float ow = dw * rstd * wv.w + bv.w;
        __nv_bfloat162 h0 = __floats2bfloat162_rn(ox, oy);
        __nv_bfloat162 h1 = __floats2bfloat162_rn(oz, ow);
        __nv_bfloat162 l0 = __floats2bfloat162_rn(ox - __bfloat162float(h0.x),
                                                  oy - __bfloat162float(h0.y));
        __nv_bfloat162 l1 = __floats2bfloat162_rn(oz - __bfloat162float(h1.x),
                                                  ow - __bfloat162float(h1.y));
        uint2 hv; hv.x = *(unsigned*)&h0; hv.y = *(unsigned*)&h1;
        uint2 lv; lv.x = *(unsigned*)&l0; lv.y = *(unsigned*)&l1;
        *(uint2*)(outh + (size_t)row * 1024 + tid * 4) = hv;
        *(uint2*)(outl + (size_t)row * 1024 + tid * 4) = lv;
    } else {
        const int vb = blockIdx.x - 2050;
        #pragma unroll
        for (int s = 0; s < 6; s++) {
            const float4* sp = (const float4*)a.src[s];
            __nv_bfloat16* hp = whi + a.dstoff[s];
            __nv_bfloat16* lp = wlo + a.dstoff[s];
            const int n4 = a.n4[s];
            for (int i = vb * 256 + tid; i < n4; i += 2048 * 256) {
                float4 f = sp[i];
                __nv_bfloat162 h0 = __floats2bfloat162_rn(f.x, f.y);
                __nv_bfloat162 h1 = __floats2bfloat162_rn(f.z, f.w);
                __nv_bfloat162 l0 = __floats2bfloat162_rn(f.x - __bfloat162float(h0.x),
                                                          f.y - __bfloat162float(h0.y));
                __nv_bfloat162 l1 = __floats2bfloat162_rn(f.z - __bfloat162float(h1.x),
                                                          f.w - __bfloat162float(h1.y));
                uint2 hv; hv.x = *(unsigned*)&h0; hv.y = *(unsigned*)&h1;
                uint2 lv; lv.x = *(unsigned*)&l0; lv.y = *(unsigned*)&l1;
                *(uint2*)(hp + (size_t)i * 4) = hv;
                *(uint2*)(lp + (size_t)i * 4) = lv;
            }
        }
    }
}

// ---------------------------------------------------------------------------
// Combine(proj split-K) + residual + LayerNorm2
// ---------------------------------------------------------------------------
__global__ void ln2_combine_kernel(const float* __restrict__ p1,
                                   const float* __restrict__ p2,
                                   const float* __restrict__ bias,
                                   const float* __restrict__ x,
                                   float* __restrict__ out,
                                   const float* __restrict__ w,
                                   const float* __restrict__ b,
                                   __nv_bfloat16* __restrict__ outh,
                                   __nv_bfloat16* __restrict__ outl) {
    __shared__ float red[32];
    int row = blockIdx.x, tid = threadIdx.x;
    const size_t ro = (size_t)row * 1024;
    float4 a  = ((const float4*)(p1 + ro))[tid];
    float4 c  = ((const float4*)(p2 + ro))[tid];
    float4 xr = ((const float4*)(x + ro))[tid];
    float4 bb = ((const float4*)bias)[tid];
    float4 v;
    v.x = a.x + c.x + bb.x + xr.x;
    v.y = a.y + c.y + bb.y + xr.y;
    v.z = a.z + c.z + bb.z + xr.z;
    v.w = a.w + c.w + bb.w + xr.w;
    ((float4*)(out + ro))[tid] = v;

    float s = v.x + v.y + v.z + v.w;
    float mean = blockReduceSum(s, red) * (1.f / 1024.f);
    float dx = v.x - mean, dy = v.y - mean, dz = v.z - mean, dw = v.w - mean;
    float ss = dx * dx + dy * dy + dz * dz + dw * dw;
    float var = blockReduceSum(ss, red) * (1.f / 1024.f);
    float rstd = rsqrtf(var + 1e-5f);
    float4 wv = ((const float4*)w)[tid];
    float4 bv = ((const float4*)b)[tid];
    float ox = dx * rstd * wv.x + bv.x;
    float oy = dy * rstd * wv.y + bv.y;
    float oz = dz * rstd * wv.z + bv.z;
    float ow = dw * rstd * wv.w + bv.w;
    __nv_bfloat162 h0 = __floats2bfloat162_rn(ox, oy);
    __nv_bfloat162 h1 = __floats2bfloat162_rn(oz, ow);
    __nv_bfloat162 l0 = __floats2bfloat162_rn(ox - __bfloat162float(h0.x),
                                              oy - __bfloat162float(h0.y));
    __nv_bfloat162 l1 = __floats2bfloat162_rn(oz - __bfloat162float(h1.x),
                                              ow - __bfloat162float(h1.y));
    uint2 hv; hv.x = *(unsigned*)&h0; hv.y = *(unsigned*)&h1;
    uint2 lv; lv.x = *(unsigned*)&l0; lv.y = *(unsigned*)&l1;
    *(uint2*)(outh + ro + tid * 4) = hv;
    *(uint2*)(outl + ro + tid * 4) = lv;
}

// ---------------------------------------------------------------------------
// fc2 split-K combine
// ---------------------------------------------------------------------------
__global__ void fc2_combine_kernel(const float* __restrict__ p1,
                                   const float* __restrict__ p2,
                                   const float* __restrict__ bias,
                                   float* __restrict__ out) {
    const int total = 2050 * 256;
    for (int i = blockIdx.x * blockDim.x + threadIdx.x; i < total;
         i += gridDim.x * blockDim.x) {
        float4 a = ((const float4*)p1)[i];
        float4 c = ((const float4*)p2)[i];
        float4 r = ((float4*)out)[i];
        float4 bb = ((const float4*)bias)[i & 255];
        r.x += a.x + c.x + bb.x;
        r.y += a.y + c.y + bb.y;
        r.z += a.z + c.z + bb.z;
        r.w += a.w + c.w + bb.w;
        ((float4*)out)[i] = r;
    }
}

// ---------------------------------------------------------------------------
// L2 norm over fused [2048 x 2048] rq|rk output -> hi/lo QKR planes
// ---------------------------------------------------------------------------
__global__ void l2norm_split_kernel(const float* __restrict__ c2,
                                    __nv_bfloat16* __restrict__ outh,
                                    __nv_bfloat16* __restrict__ outl) {
    __shared__ float red[32];
    int i = blockIdx.x, tid = threadIdx.x;
    const int srcRow = i & 2047;
    const int colOff = (i >> 11) * 1024;
    const float4* p = (const float4*)(c2 + (size_t)srcRow * 2048 + colOff);
    float4 v = p[tid];
    float ss = v.x * v.x + v.y * v.y + v.z * v.z + v.w * v.w;
    float tot = blockReduceSum(ss, red);
    float sc = 1.f / fmaxf(sqrtf(tot), 1e-12f);
    float ox = v.x * sc, oy = v.y * sc, oz = v.z * sc, ow = v.w * sc;
    __nv_bfloat162 h0 = __floats2bfloat162_rn(ox, oy);
    __nv_bfloat162 h1 = __floats2bfloat162_rn(oz, ow);
    __nv_bfloat162 l0 = __floats2bfloat162_rn(ox - __bfloat162float(h0.x),
                                              oy - __bfloat162float(h0.y));
    __nv_bfloat162 l1 = __floats2bfloat162_rn(oz - __bfloat162float(h1.x),
                                              ow - __bfloat162float(h1.y));
    uint2 hv; hv.x = *(unsigned*)&h0; hv.y = *(unsigned*)&h1;
    uint2 lv; lv.x = *(unsigned*)&l0; lv.y = *(unsigned*)&l1;
    *(uint2*)(outh + (size_t)i * 1024 + tid * 4) = hv;
    *(uint2*)(outl + (size_t)i * 1024 + tid * 4) = lv;
}

// ---------------------------------------------------------------------------
// bf16 tensor-core NT GEMM core.
// TERMS=3: 2-stage, 4 planes/stage (Ah,Al,Bh,Bl), 2 barriers/iter.
// TERMS=2: 3-stage, 3 planes/stage (Ah,Al,Bh), 1 barrier/iter (post-barrier
//          issue targets the stage everyone finished last iteration).
// ---------------------------------------------------------------------------
#define EPI_NONE        0
#define EPI_BIAS        1
#define EPI_BIAS2       2
#define EPI_GELU_SPLIT  3

#define KSTRIDE 40
#define TILE_BF16 (128 * KSTRIDE)
#define PLANE_BYTES (TILE_BF16 * 2)          // 10240
#define GEMM_SMEM3 (2 * 4 * PLANE_BYTES)     // 81920 (3-term)
#define GEMM_SMEM2 (3 * 3 * PLANE_BYTES)     // 92160 (2-term)

__device__ __forceinline__ void mma_bf16(float* d, const unsigned* a, const unsigned* b) {
    asm volatile(
        "mma.sync.aligned.m16n8k16.row.col.f32.bf16.bf16.f32 "
        "{%0,%1,%2,%3}, {%4,%5,%6,%7}, {%8,%9}, {%0,%1,%2,%3};"
        : "+f"(d[0]), "+f"(d[1]), "+f"(d[2]), "+f"(d[3])
        : "r"(a[0]), "r"(a[1]), "r"(a[2]), "r"(a[3]), "r"(b[0]), "r"(b[1]));
}

__device__ __forceinline__ void ldsm4(unsigned addr, unsigned& r0, unsigned& r1,
                                      unsigned& r2, unsigned& r3) {
    asm volatile("ldmatrix.sync.aligned.m8n8.x4.shared.b16 {%0,%1,%2,%3}, [%4];"
                 : "=r"(r0), "=r"(r1), "=r"(r2), "=r"(r3) : "r"(addr));
}

__device__ __forceinline__ void cpasync16(unsigned dst, const void* src, unsigned sz) {
    asm volatile("cp.async.ca.shared.global [%0], [%1], 16, %2;"
                 :: "r"(dst), "l"(src), "r"(sz));
}

template <int EPI, int TERMS>
__device__ __forceinline__ void gemm_core(
    const __nv_bfloat16* __restrict__ Ah, const __nv_bfloat16* __restrict__ Al,
    const __nv_bfloat16* __restrict__ Bh, const __nv_bfloat16* __restrict__ Bl,
    const float* __restrict__ bias, const float* __restrict__ extra,
    float* __restrict__ C, __nv_bfloat16* __restrict__ Ch, __nv_bfloat16* __restrict__ Cl,
    int M, int N, int Kd, int lda, int ldb,
    long sA, long sB, long sC, long sCk, int KS,
    int bxv, int byv, int bzv) {

    const int PLANES = (TERMS == 2) ? 3 : 4;
    const int zb = bzv / KS;
    const int ks = bzv % KS;
    Ah += (long)zb * sA + (long)ks * Kd;  Al += (long)zb * sA + (long)ks * Kd;
    Bh += (long)zb * sB + (long)ks * Kd;  Bl += (long)zb * sB + (long)ks * Kd;
    const long cOff = (long)zb * sC + (long)ks * sCk;

    extern __shared__ __nv_bfloat16 sm[];

    const int tid  = threadIdx.x;
    const int lane = tid & 31;
    const int wid  = tid >> 5;
    const int wr   = wid & 3;
    const int wc   = wid >> 2;
    const int g    = lane >> 2;
    const int tig  = lane & 3;
    const int bm   = byv * 128;
    const int bn   = bxv * 128;

    float acc[2][8][4];
    #pragma unroll
    for (int mi = 0; mi < 2; mi++)
        #pragma unroll
        for (int ni = 0; ni < 8; ni++)
            #pragma unroll
            for (int r = 0; r < 4; r++) acc[mi][ni][r] = 0.f;

    const int ldRow = tid >> 1;
    const int half  = tid & 1;
    const int aRow  = bm + ldRow;
    const unsigned aSz = (aRow < M) ? 16u : 0u;
    const long aOff = (long)((aRow < M) ? aRow : 0) * lda + half * 16;
    const long bOff = (long)(bn + ldRow) * ldb + half * 16;
    const __nv_bfloat16* aH = Ah + aOff;
    const __nv_bfloat16* aL = Al + aOff;
    const __nv_bfloat16* bH = Bh + bOff;
    const __nv_bfloat16* bL = Bl + bOff;

    const unsigned smBase = (unsigned)__cvta_generic_to_shared(sm);
    const unsigned dA0 = smBase + 2u * (unsigned)(ldRow * KSTRIDE + half * 16);
    const unsigned stagePitch = (unsigned)(PLANES * PLANE_BYTES);

    const int aRowL = wr * 32 + (lane & 7) + ((lane >> 3) & 1) * 8;
    const int aKL   = ((lane >> 4) & 1) * 8;
    const unsigned aLaneOff = (unsigned)(aRowL * KSTRIDE + aKL);
    const int bRowL = wc * 64 + (lane & 7) + ((lane >> 4) & 1) * 8;
    const int bKL   = ((lane >> 3) & 1) * 8;
    const unsigned bLaneOff = (unsigned)(bRowL * KSTRIDE + bKL);

    const int nIter = Kd >> 5;

    // planes: Ah=+0, Al=+1, Bh=+2, Bl=+3 (3-term only)
    #define ISSUE(st, itv) do {                                              \
        const long k0 = (long)(itv) * 32;                                    \
        unsigned d0 = dA0 + (unsigned)(st) * stagePitch;                     \
        cpasync16(d0,                    aH + k0,     aSz);                  \
        cpasync16(d0 + 16,               aH + k0 + 8, aSz);                  \
        cpasync16(d0 + PLANE_BYTES,      aL + k0,     aSz);                  \
        cpasync16(d0 + PLANE_BYTES + 16, aL + k0 + 8, aSz);                  \
        cpasync16(d0 + 2 * PLANE_BYTES,      bH + k0,     16u);              \
        cpasync16(d0 + 2 * PLANE_BYTES + 16, bH + k0 + 8, 16u);              \
        if (TERMS == 3) {                                                    \
            cpasync16(d0 + 3 * PLANE_BYTES,      bL + k0,     16u);          \
            cpasync16(d0 + 3 * PLANE_BYTES + 16, bL + k0 + 8, 16u);          \
        }                                                                    \
        asm volatile("cp.async.commit_group;");                              \
    } while (0)

    #define COMPUTE(stv) do {                                                \
        const unsigned pBase = (unsigned)((stv) * PLANES * TILE_BF16);       \
        _Pragma("unroll")                                                    \
        for (int ksl = 0; ksl < 2; ksl++) {                                  \
            const int kb = ksl * 16;                                         \
            unsigned Ahf[2][4], Alf[2][4], Bhf[8][2], Blf[8][2];             \
            _Pragma("unroll")                                                \
            for (int mi = 0; mi < 2; mi++) {                                 \
                unsigned off = (unsigned)(mi * 16 * KSTRIDE + kb) + aLaneOff;\
                ldsm4(smBase + 2u * (pBase + off),                           \
                      Ahf[mi][0], Ahf[mi][1], Ahf[mi][2], Ahf[mi][3]);       \
                ldsm4(smBase + 2u * (pBase + TILE_BF16 + off),               \
                      Alf[mi][0], Alf[mi][1], Alf[mi][2], Alf[mi][3]);       \
            }                                                                \
            _Pragma("unroll")                                                \
            for (int j = 0; j < 4; j++) {                                    \
                unsigned off = (unsigned)(j * 16 * KSTRIDE + kb) + bLaneOff; \
                ldsm4(smBase + 2u * (pBase + 2 * TILE_BF16 + off),           \
                      Bhf[j * 2][0], Bhf[j * 2][1],                          \
                      Bhf[j * 2 + 1][0], Bhf[j * 2 + 1][1]);                 \
                if (TERMS == 3) {                                            \
                    ldsm4(smBase + 2u * (pBase + 3 * TILE_BF16 + off),       \
                          Blf[j * 2][0], Blf[j * 2][1],                      \
                          Blf[j * 2 + 1][0], Blf[j * 2 + 1][1]);             \
                }                                                            \
            }                                                                \
            _Pragma("unroll")                                                \
            for (int mi = 0; mi < 2; mi++)                                   \
                _Pragma("unroll")                                            \
                for (int ni = 0; ni < 8; ni++) {                             \
                    mma_bf16(acc[mi][ni], Ahf[mi], Bhf[ni]);                 \
                    mma_bf16(acc[mi][ni], Alf[mi], Bhf[ni]);                 \
                    if (TERMS == 3) mma_bf16(acc[mi][ni], Ahf[mi], Blf[ni]); \
                }                                                            \
        }                                                                    \
    } while (0)

    if (TERMS == 2) {
        // 3-stage, single barrier per iteration
        ISSUE(0, 0);
        if (nIter > 1) ISSUE(1, 1);
        for (int it = 0; it < nIter; ++it) {
            if (it == nIter - 1) asm volatile("cp.async.wait_group 0;");
            else                 asm volatile("cp.async.wait_group 1;");
            __syncthreads();
            if (it + 2 < nIter) ISSUE((it + 2) % 3, it + 2);
            COMPUTE(it % 3);
        }
    } else {
        // 2-stage, two barriers per iteration
        ISSUE(0, 0);
        if (nIter > 1) ISSUE(1, 1);
        for (int it = 0; it < nIter; ++it) {
            if (it == nIter - 1) asm volatile("cp.async.wait_group 0;");
            else                 asm volatile("cp.async.wait_group 1;");
            __syncthreads();
            COMPUTE(it & 1);
            __syncthreads();
            if (it + 2 < nIter) ISSUE(it & 1, it + 2);
        }
    }
    #undef ISSUE
    #undef COMPUTE

    #pragma unroll
    for (int mi = 0; mi < 2; mi++) {
        #pragma unroll
        for (int rr = 0; rr < 2; rr++) {
            const int m = bm + wr * 32 + mi * 16 + g + rr * 8;
            if (m >= M) continue;
            #pragma unroll
            for (int ni = 0; ni < 8; ni++) {
                #pragma unroll
                for (int cc = 0; cc < 2; cc++) {
                    const int n = bn + wc * 64 + ni * 8 + tig * 2 + cc;
                    float v = acc[mi][ni][rr * 2 + cc];
                    const long idx = cOff + (long)m * N + n;
                    if (EPI == EPI_NONE) {
                        C[idx] = v;
                    } else if (EPI == EPI_BIAS) {
                        C[idx] = v + bias[n];
                    } else if (EPI == EPI_BIAS2) {
                        const int hN = N >> 1;
                        C[idx] = v + (n < hN ? bias[n] : extra[n - hN]);
                    } else if (EPI == EPI_GELU_SPLIT) {
                        v += bias[n];
                        v = 0.5f * v * (1.0f + erff(v * 0.70710678118654752f));
                        split1(v, Ch + idx, Cl + idx);
                    }
                }
            }
        }
    }
}

template <int EPI, int TERMS>
__global__ __launch_bounds__(256, 2) void gemm_one(
    const __nv_bfloat16* __restrict__ Ah, const __nv_bfloat16* __restrict__ Al,
    const __nv_bfloat16* __restrict__ Bh, const __nv_bfloat16* __restrict__ Bl,
    const float* __restrict__ bias, const float* __restrict__ extra,
    float* __restrict__ C, __nv_bfloat16* __restrict__ Ch, __nv_bfloat16* __restrict__ Cl,
    int M, int N, int Kd, int lda, int ldb,
    long sA, long sB, long sC, long sCk, int KS) {
    gemm_core<EPI, TERMS>(Ah, Al, Bh, Bl, bias, extra, C, Ch, Cl,
                          M, N, Kd, lda, ldb, sA, sB, sC, sCk, KS,
                          blockIdx.x, blockIdx.y, blockIdx.z);
}

// merged scores (blocks 0..255, 3-term split-K) + qkv (blocks 256..663, 2-term)
__global__ __launch_bounds__(256, 2) void gemm_scores_qkv(
    const __nv_bfloat16* __restrict__ QKRh, const __nv_bfloat16* __restrict__ QKRl,
    float* __restrict__ SC, long sCk,
    const __nv_bfloat16* __restrict__ XNh, const __nv_bfloat16* __restrict__ XNl,
    const __nv_bfloat16* __restrict__ WQh, const __nv_bfloat16* __restrict__ WQl,
    const float* __restrict__ qkv_b, float* __restrict__ QKV) {
    if (blockIdx.x < 256) {
        const int l = blockIdx.x;
        gemm_core<EPI_NONE, 3>(QKRh, QKRl, QKRh + 2048ull * 1024, QKRl + 2048ull * 1024,
                               nullptr, nullptr, SC, nullptr, nullptr,
                               1024, 1024, 512, 1024, 1024,
                               1024ll * 1024, 1024ll * 1024, 1024ll * 1024, sCk, 2,
                               l & 7, (l >> 3) & 7, l >> 6);
    } else {
        const int l = blockIdx.x - 256;
        gemm_core<EPI_BIAS, 2>(XNh, XNl, WQh, WQl, qkv_b, nullptr,
                               QKV, nullptr, nullptr,
                               2050, 3072, 1024, 1024, 1024, 0, 0, 0, 0, 1,
                               l % 24, l / 24, 0);
    }
}

// ---------------------------------------------------------------------------
// Merged attention with integrated top-k:
// blocks [0,2048): per-row topk (from SC partials + bias + diag) then routed
// patch attention (warp-per-head). blocks [2048,2080): CLS attention.
// ---------------------------------------------------------------------------
__global__ __launch_bounds__(512) void attn_kernel(
        const float* __restrict__ qkv,
        const float* __restrict__ sc1,
        const float* __restrict__ sc2,
        const float* __restrict__ pos_bias,
        __nv_bfloat16* __restrict__ atth,
        __nv_bfloat16* __restrict__ attl) {
    const int tid = threadIdx.x, lane = tid & 31;
    if (blockIdx.x < 2048) {
        __shared__ float wv[16][32];
        __shared__ int   wi[16][32];
        __shared__ float sv[32];
        __shared__ int   si[32];
        __shared__ int   rt[32];
        __shared__ float lw[32];
        const int bp = blockIdx.x, b = bp >> 10, p = bp & 1023;
        const int w = tid >> 5;

        // ---- integrated top-32 over this row ----
        {
            const float* s1 = sc1 + (size_t)bp * 1024;
            const float* s2 = sc2 + (size_t)bp * 1024;
            const float* pb = pos_bias + (size_t)p * 1024;
            float v[2]; int id2[2];
            #pragma unroll
            for (int c = 0; c < 2; c++) {
                int id = w * 64 + c * 32 + lane;
                float val = s1[id] + s2[id] + pb[id];
                if (id == p) val = -1e9f;
                v[c] = val;
                id2[c] = id;
            }
            for (int it = 0; it < 32; it++) {
                float bv = v[0]; int bi = id2[0]; int bs = 0;
                if (v[1] > bv || (v[1] == bv && id2[1] < bi)) { bv = v[1]; bi = id2[1]; bs = 1; }
                float cv = bv; int ci = bi;
                #pragma unroll
                for (int o = 16; o; o >>= 1) {
                    float ov = __shfl_xor_sync(0xffffffffu, cv, o);
                    int   oi = __shfl_xor_sync(0xffffffffu, ci, o);
                    if (ov > cv || (ov == cv && oi < ci)) { cv = ov; ci = oi; }
                }
                if (lane == 0) { wv[w][it] = cv; wi[w][it] = ci; }
                if (ci == bi) v[bs] = -3.4e38f;
            }
            __syncthreads();
            if (w == 0) {
                int ptr = 0;
                for (int it = 0; it < 32; it++) {
                    float cv = (lane < 16 && ptr < 32) ? wv[lane][ptr] : -3.4e38f;
                    int   ci = (lane < 16 && ptr < 32) ? wi[lane][ptr] : 0x7fffffff;
                    float bv = cv; int bi = ci;
                    #pragma unroll
                    for (int o = 16; o; o >>= 1) {
                        float ov = __shfl_xor_sync(0xffffffffu, bv, o);
                        int   oi = __shfl_xor_sync(0xffffffffu, bi, o);
                        if (ov > bv || (ov == bv && oi < bi)) { bv = ov; bi = oi; }
                    }
                    if (lane < 16 && ci == bi && ptr < 32) ptr++;
                    if (lane == 0) { sv[it] = bv; si[it] = bi; }
                }
            }
            __syncthreads();
            if (tid < 32) {
                float t = sv[tid] * INV_TEMP;
                float tmax = sv[0] * INV_TEMP;
                float e = expf(t - tmax);
                float z = e;
                #pragma unroll
                for (int o = 16; o; o >>= 1) z += __shfl_xor_sync(0xffffffffu, z, o);
                float lwv = t - (tmax + logf(z));
                rt[tid] = si[tid] + 1;
                lw[tid] = fmaxf(lwv, -10.f);
            }
            __syncthreads();
        }

        // ---- routed patch attention (warp-per-head) ----
        const int h = w;
        const float* base = qkv + (size_t)b * SS * 3072;
        const float* qp = base + (size_t)(p + 1) * 3072 + h * 64;
        const float q0 = qp[lane], q1 = qp[lane + 32];

        float myscore = 0.f;
        #pragma unroll
        for (int kb = 0; kb < 32; kb += 8) {
            float k0[8], k1[8];
            #pragma unroll
            for (int j = 0; j < 8; j++) {
                const float* kp = base + (size_t)rt[kb + j] * 3072 + 1024 + h * 64;
                k0[j] = kp[lane];
                k1[j] = kp[lane + 32];
            }
            #pragma unroll
            for (int j = 0; j < 8; j++) {
                float d = q0 * k0[j] + q1 * k1[j];
                #pragma unroll
                for (int o = 16; o; o >>= 1) d += __shfl_xor_sync(0xffffffffu, d, o);
                if (lane == kb + j) myscore = d * SCALE_ + lw[lane];
            }
        }

        float m = myscore;
        #pragma unroll
        for (int o = 16; o; o >>= 1) m = fmaxf(m, __shfl_xor_sync(0xffffffffu, m, o));
        float e = expf(myscore - m);
        float z = e;
        #pragma unroll
        for (int o = 16; o; o >>= 1) z += __shfl_xor_sync(0xffffffffu, z, o);
        const float pw = e / z;

        float o0 = 0.f, o1 = 0.f;
        #pragma unroll
        for (int kb = 0; kb < 32; kb += 8) {
            float v0[8], v1[8];
            #pragma unroll
            for (int j = 0; j < 8; j++) {
                const float* vp = base + (size_t)rt[kb + j] * 3072 + 2048 + h * 64;
                v0[j] = vp[lane];
                v1[j] = vp[lane + 32];
            }
            #pragma unroll
            for (int j = 0; j < 8; j++) {
                float wj = __shfl_sync(0xffffffffu, pw, kb + j);
                o0 += wj * v0[j];
                o1 += wj * v1[j];
            }
        }

        const size_t idx = ((size_t)b * SS + p + 1) * 1024 + h * 64 + lane;
        split1(o0, atth + idx, attl + idx);
        split1(o1, atth + idx + 32, attl + idx + 32);
    } else {
        __shared__ float q[64];
        __shared__ float sp[SS];
        __shared__ float red[32];
        __shared__ float po[8][64];
        const int bh = blockIdx.x - 2048, b = bh >> 4, h = bh & 15;
        const float* base = qkv + (size_t)b * SS * 3072;
        if (tid < 64) q[tid] = base[h * 64 + tid];
        __syncthreads();

        float lmax = -3.4e38f;
        for (int j = tid; j < SS; j += 512) {
            const float* kr = base + (size_t)j * 3072 + 1024 + h * 64;
            float d = 0.f;
            #pragma unroll
            for (int dd = 0; dd < 64; dd++) d += q[dd] * kr[dd];
            d *= SCALE_;
            sp[j] = d;
            lmax = fmaxf(lmax, d);
        }
        float M = blockReduceMax512(lmax, red);
        float ls = 0.f;
        for (int j = tid; j < SS; j += 512) {
            float e = expf(sp[j] - M);
            sp[j] = e;
            ls += e;
        }
        float Z = blockReduceSum512(ls, red);

        int g = tid >> 6, d = tid & 63;
        float o = 0.f;
        for (int j = g; j < SS; j += 8)
            o += sp[j] * base[(size_t)j * 3072 + 2048 + h * 64 + d];
        po[g][d] = o;
        __syncthreads();
        if (tid < 64) {
            float r = 0.f;
            #pragma unroll
            for (int gg = 0; gg < 8; gg++) r += po[gg][tid];
            r /= Z;
            size_t idx = (size_t)b * SS * 1024 + h * 64 + tid;
            split1(r, atth + idx, attl + idx);
        }
    }
}

// ---------------------------------------------------------------------------
// Orchestration
// ---------------------------------------------------------------------------
extern "C" void kernel_launch(void* const* d_in, const int* in_sizes, int n_in,
                              void* d_out, int out_size) {
    const float* x        = (const float*)d_in[0];
    const float* n1w      = (const float*)d_in[1];
    const float* n1b      = (const float*)d_in[2];
    const float* rq_w     = (const float*)d_in[3];
    const float* rq_b     = (const float*)d_in[4];
    const float* rk_w     = (const float*)d_in[5];
    const float* rk_b     = (const float*)d_in[6];
    const float* pos_bias = (const float*)d_in[7];
    const float* qkv_w    = (const float*)d_in[8];
    const float* qkv_b    = (const float*)d_in[9];
    const float* proj_w   = (const float*)d_in[10];
    const float* proj_b   = (const float*)d_in[11];
    const float* n2w      = (const float*)d_in[12];
    const float* n2b      = (const float*)d_in[13];
    const float* fc1_w    = (const float*)d_in[14];
    const float* fc1_b    = (const float*)d_in[15];
    const float* fc2_w    = (const float*)d_in[16];
    const float* fc2_b    = (const float*)d_in[17];
    float* out = (float*)d_out;

    void* sp = nullptr;
    cudaGetSymbolAddress(&sp, g_scratch);
    float* SCR = (float*)sp;
    float* C2  = SCR + O_QR;
    float* SC  = SCR + O_SC;
    float* SC2 = SCR + O_SC2;
    float* QKV = SCR + O_QKV;
    float* P1  = SCR + O_P1;
    float* P2  = SCR + O_P2;
    __nv_bfloat16* XNh  = (__nv_bfloat16*)(SCR + O_XNH);
    __nv_bfloat16* XNl  = (__nv_bfloat16*)(SCR + O_XNL);
    __nv_bfloat16* QKRh = (__nv_bfloat16*)(SCR + O_QKRH);
    __nv_bfloat16* QKRl = (__nv_bfloat16*)(SCR + O_QKRL);
    __nv_bfloat16* ATTh = (__nv_bfloat16*)(SCR + O_ATTH);
    __nv_bfloat16* ATTl = (__nv_bfloat16*)(SCR + O_ATTL);
    __nv_bfloat16* HNh  = (__nv_bfloat16*)(SCR + O_HNH);
    __nv_bfloat16* HNl  = (__nv_bfloat16*)(SCR + O_HNL);
    __nv_bfloat16* HHh  = (__nv_bfloat16*)(SCR + O_HHH);
    __nv_bfloat16* HHl  = (__nv_bfloat16*)(SCR + O_HHL);
    __nv_bfloat16* WH   = (__nv_bfloat16*)(SCR + O_WH);
    __nv_bfloat16* WL   = (__nv_bfloat16*)(SCR + O_WL);

    cudaFuncSetAttribute(gemm_one<EPI_BIAS2, 3>,
                         cudaFuncAttributeMaxDynamicSharedMemorySize, GEMM_SMEM3);
    cudaFuncSetAttribute(gemm_one<EPI_NONE, 2>,
                         cudaFuncAttributeMaxDynamicSharedMemorySize, GEMM_SMEM2);
    cudaFuncSetAttribute(gemm_one<EPI_GELU_SPLIT, 3>,
                         cudaFuncAttributeMaxDynamicSharedMemorySize, GEMM_SMEM3);
    cudaFuncSetAttribute(gemm_scores_qkv,
                         cudaFuncAttributeMaxDynamicSharedMemorySize, GEMM_SMEM2);

    // 0+1. merged weight split + LayerNorm1
    WSplit6 wargs;
    wargs.src[0] = rq_w;   wargs.dstoff[0] = (long)W_RQ;   wargs.n4[0] = 1048576 / 4;
    wargs.src[1] = rk_w;   wargs.dstoff[1] = (long)W_RK;   wargs.n4[1] = 1048576 / 4;
    wargs.src[2] = qkv_w;  wargs.dstoff[2] = (long)W_QKV;  wargs.n4[2] = 3145728 / 4;
    wargs.src[3] = proj_w; wargs.dstoff[3] = (long)W_PROJ; wargs.n4[3] = 1048576 / 4;
    wargs.src[4] = fc1_w;  wargs.dstoff[4] = (long)W_FC1;  wargs.n4[4] = 4194304 / 4;
    wargs.src[5] = fc2_w;  wargs.dstoff[5] = (long)W_FC2;  wargs.n4[5] = 4194304 / 4;
    ln1_splitw_kernel<<<4098, 256>>>(wargs, WH, WL, x, n1w, n1b, XNh, XNl);

    // 2. Fused routing projections (3-term)
    dim3 gR(16, 8, 2);
    gemm_one<EPI_BIAS2, 3><<<gR, 256, GEMM_SMEM3>>>(
        XNh + 1024, XNl + 1024, WH + W_RQ, WL + W_RQ, rq_b, rk_b,
        C2, nullptr, nullptr, 1024, 2048, 1024, 1024, 1024,
        (long)SS * DD, 0, (long)PP * 2048, 0, 1);

    // 3. L2 normalize + demux
    l2norm_split_kernel<<<4096, 256>>>(C2, QKRh, QKRl);

    // 4+6. merged scores (split-K, 3-term) + qkv (2-term, 3-stage): grid 664
    gemm_scores_qkv<<<664, 256, GEMM_SMEM2>>>(
        QKRh, QKRl, SC, (long)(SC2 - SC),
        XNh, XNl, WH + W_QKV, WL + W_QKV, qkv_b, QKV);

    // 5+7+8. merged topk + patch attention + CLS attention: grid 2080
    attn_kernel<<<2080, 512>>>(QKV, SC, SC2, pos_bias, ATTh, ATTl);

    // 9. Output projection, split-K=2 (2-term, 3-stage)
    dim3 gP(8, 17, 2);
    gemm_one<EPI_NONE, 2><<<gP, 256, GEMM_SMEM2>>>(
        ATTh, ATTl, WH + W_PROJ, WL + W_PROJ, nullptr, nullptr,
        P1, nullptr, nullptr, 2050, 1024, 512, 1024, 1024,
        0, 0, 0, (long)(P2 - P1), 2);

    // 10. Combine + residual + LayerNorm 2
    ln2_combine_kernel<<<BB * SS, 256>>>(P1, P2, proj_b, x, out, n2w, n2b, HNh, HNl);

    // 11. FC1 + exact GELU (3-term)
    dim3 gF1(32, 17, 1);
    gemm_one<EPI_GELU_SPLIT, 3><<<gF1, 256, GEMM_SMEM3>>>(
        HNh, HNl, WH + W_FC1, WL + W_FC1, fc1_b, nullptr,
        nullptr, HHh, HHl, 2050, 4096, 1024, 1024, 1024, 0, 0, 0, 0, 1);

    // 12. FC2, split-K=2 (2-term, 3-stage), combine + residual
    dim3 gF2(8, 17, 2);
    gemm_one<EPI_NONE, 2><<<gF2, 256, GEMM_SMEM2>>>(
        HHh, HHl, WH + W_FC2, WL + W_FC2, nullptr, nullptr,
        P1, nullptr, nullptr, 2050, 1024, 2048, 4096, 4096,
        0, 0, 0, (long)(P2 - P1), 2);
    fc2_combine_kernel<<<1024, 256>>>(P1, P2, fc2_b, out);

    (void)in_sizes; (void)n_in; (void)out_size;
}